// round 9
// baseline (speedup 1.0000x reference)
#include <cuda_runtime.h>
#include <cuda_bf16.h>
#include <cstdint>

// ---------------------------------------------------------------------------
// 3-layer GraphSAGE (mean aggregation), fp32-grade via bf16 hi/lo pairs.
//   activations stored as TWO bf16 arrays (hi, lo); value = hi + lo.
//   aggregation: CSR segment-mean gather (no float atomics)
//   GEMM: mma.sync m16n8k16 bf16, 3 products (AhBh + AlBh + AhBl),
//         cp.async double-buffered pipeline, zero unpack math in the hot loop.
// N = 100000, E = 1600000, dims 128 -> 256 -> 256 -> 256.
// ---------------------------------------------------------------------------

#define NN 100000
#define NE 1600000
#define CMAX 256

// ---------------- split activation buffers (hi / lo bf16) ------------------
__device__ __align__(16) __nv_bfloat16 g_xh  [(size_t)NN * 128];
__device__ __align__(16) __nv_bfloat16 g_xl  [(size_t)NN * 128];
__device__ __align__(16) __nv_bfloat16 g_aggh[(size_t)NN * CMAX];
__device__ __align__(16) __nv_bfloat16 g_aggl[(size_t)NN * CMAX];
__device__ __align__(16) __nv_bfloat16 g_h0h [(size_t)NN * CMAX];
__device__ __align__(16) __nv_bfloat16 g_h0l [(size_t)NN * CMAX];
__device__ __align__(16) __nv_bfloat16 g_h1h [(size_t)NN * CMAX];
__device__ __align__(16) __nv_bfloat16 g_h1l [(size_t)NN * CMAX];

// split transposed weights [N=256, K] (K contiguous)
#define WBUF_TOTAL (2 * 128 * 256 + 4 * 256 * 256)
__device__ __align__(16) __nv_bfloat16 g_Wh[WBUF_TOTAL];
__device__ __align__(16) __nv_bfloat16 g_Wl[WBUF_TOTAL];

// CSR build
#define SCAN_B 512
#define NB1 ((NN + SCAN_B - 1) / SCAN_B)
__device__ int g_cnt[NN];
__device__ int g_pos[NN];
__device__ int g_rowptr[NN];
__device__ int g_srcs[NE];
__device__ int g_scan[NN];
__device__ int g_part[NB1];
__device__ int g_partscan[NB1];

// ---------------------------------------------------------------------------
// helpers
// ---------------------------------------------------------------------------
__device__ __forceinline__ void split_bf16(float v, __nv_bfloat16& h, __nv_bfloat16& l) {
    h = __float2bfloat16_rn(v);
    l = __float2bfloat16_rn(v - __bfloat162float(h));
}
__device__ __forceinline__ uint32_t pack2(__nv_bfloat16 a, __nv_bfloat16 b) {
    __nv_bfloat162 p = __halves2bfloat162(a, b);   // a = low (first element)
    return *reinterpret_cast<uint32_t*>(&p);
}
__device__ __forceinline__ void acc_u32pair(float& a0, float& a1, uint32_t u) {
    a0 += __uint_as_float(u << 16);
    a1 += __uint_as_float(u & 0xFFFF0000u);
}
__device__ __forceinline__ void cpa16(uint32_t saddr, const void* g, int sz) {
    asm volatile("cp.async.ca.shared.global [%0], [%1], 16, %2;"
                 :: "r"(saddr), "l"(g), "r"(sz) : "memory");
}
__device__ __forceinline__ uint32_t smem_u32p(const void* p) {
    uint32_t a;
    asm("{ .reg .u64 t; cvta.to.shared.u64 t, %1; cvt.u32.u64 %0, t; }" : "=r"(a) : "l"(p));
    return a;
}
__device__ __forceinline__ void mma_bf16(float* c, const uint32_t* a, const uint32_t* b) {
    asm volatile(
        "mma.sync.aligned.m16n8k16.row.col.f32.bf16.bf16.f32 "
        "{%0,%1,%2,%3}, {%4,%5,%6,%7}, {%8,%9}, {%0,%1,%2,%3};"
        : "+f"(c[0]), "+f"(c[1]), "+f"(c[2]), "+f"(c[3])
        : "r"(a[0]), "r"(a[1]), "r"(a[2]), "r"(a[3]), "r"(b[0]), "r"(b[1]));
}

// ---------------------------------------------------------------------------
// CSR build kernels
// ---------------------------------------------------------------------------
__global__ void k_zero_cnt() {
    int i = blockIdx.x * blockDim.x + threadIdx.x;
    if (i < NN) { g_cnt[i] = 0; g_pos[i] = 0; }
}
__global__ void k_hist(const int* __restrict__ dst) {
    int i = blockIdx.x * blockDim.x + threadIdx.x;
    if (i < NE) atomicAdd(&g_cnt[dst[i]], 1);
}
__global__ void k_scan1() {
    __shared__ int s[SCAN_B];
    int t = threadIdx.x;
    int idx = blockIdx.x * SCAN_B + t;
    int v = (idx < NN) ? g_cnt[idx] : 0;
    s[t] = v;
    __syncthreads();
#pragma unroll
    for (int off = 1; off < SCAN_B; off <<= 1) {
        int tmp = (t >= off) ? s[t - off] : 0;
        __syncthreads();
        s[t] += tmp;
        __syncthreads();
    }
    if (idx < NN) g_scan[idx] = s[t];
    if (t == SCAN_B - 1) g_part[blockIdx.x] = s[t];
}
__global__ void k_scan2() {
    __shared__ int s[256];
    int t = threadIdx.x;
    int v = (t < NB1) ? g_part[t] : 0;
    s[t] = v;
    __syncthreads();
#pragma unroll
    for (int off = 1; off < 256; off <<= 1) {
        int tmp = (t >= off) ? s[t - off] : 0;
        __syncthreads();
        s[t] += tmp;
        __syncthreads();
    }
    if (t < NB1) g_partscan[t] = s[t];
}
__global__ void k_scan3() {
    int idx = blockIdx.x * blockDim.x + threadIdx.x;
    if (idx < NN) {
        int b = idx / SCAN_B;
        int boff = (b > 0) ? g_partscan[b - 1] : 0;
        g_rowptr[idx] = g_scan[idx] - g_cnt[idx] + boff;
    }
}
__global__ void k_place(const int* __restrict__ src, const int* __restrict__ dst) {
    int i = blockIdx.x * blockDim.x + threadIdx.x;
    if (i < NE) {
        int d = dst[i];
        int pos = g_rowptr[d] + atomicAdd(&g_pos[d], 1);
        g_srcs[pos] = src[i];
    }
}

// ---------------------------------------------------------------------------
// prep: split x; split+transpose weights
// ---------------------------------------------------------------------------
__global__ void k_prep_x(const float* __restrict__ x) {
    int i = blockIdx.x * blockDim.x + threadIdx.x;   // handles 2 elements
    if (i >= NN * 64) return;
    float2 v = reinterpret_cast<const float2*>(x)[i];
    __nv_bfloat16 h0, l0, h1, l1;
    split_bf16(v.x, h0, l0);
    split_bf16(v.y, h1, l1);
    reinterpret_cast<uint32_t*>(g_xh)[i] = pack2(h0, h1);
    reinterpret_cast<uint32_t*>(g_xl)[i] = pack2(l0, l1);
}
__global__ void k_prep_w(const float* __restrict__ W, int K, int outoff) {
    int i = blockIdx.x * blockDim.x + threadIdx.x;
    if (i >= K * 256) return;
    int k = i >> 8, n = i & 255;
    __nv_bfloat16 h, l;
    split_bf16(W[i], h, l);
    g_Wh[outoff + n * K + k] = h;
    g_Wl[outoff + n * K + k] = l;
}

// ---------------------------------------------------------------------------
// aggregation: segment-mean gather over split hi/lo arrays.
// one warp per node; lane covers C/32 channels.
// ---------------------------------------------------------------------------
template <int C>   // 128 or 256
__global__ void k_aggregate(int xsel) {
    const __nv_bfloat16 *xh, *xl;
    if (xsel == 0)      { xh = g_xh;  xl = g_xl;  }
    else if (xsel == 1) { xh = g_h0h; xl = g_h0l; }
    else                { xh = g_h1h; xl = g_h1l; }

    int node = (blockIdx.x * blockDim.x + threadIdx.x) >> 5;
    int lane = threadIdx.x & 31;
    if (node >= NN) return;

    constexpr int CPL = C / 32;          // channels per lane: 4 or 8
    constexpr int NU  = CPL / 2;         // u32 words per lane: 2 or 4

    int beg = g_rowptr[node];
    int len = g_cnt[node];
    int end = beg + len;

    float acc[CPL];
#pragma unroll
    for (int i = 0; i < CPL; ++i) acc[i] = 0.0f;

    const int u0 = lane * NU;

    auto gather_one = [&](int s) {
        const uint32_t* rh = reinterpret_cast<const uint32_t*>(xh + (size_t)s * C);
        const uint32_t* rl = reinterpret_cast<const uint32_t*>(xl + (size_t)s * C);
        if (NU == 4) {
            uint4 vh = *reinterpret_cast<const uint4*>(rh + u0);
            uint4 vl = *reinterpret_cast<const uint4*>(rl + u0);
            acc_u32pair(acc[0], acc[1], vh.x); acc_u32pair(acc[0], acc[1], vl.x);
            acc_u32pair(acc[2], acc[3], vh.y); acc_u32pair(acc[2], acc[3], vl.y);
            acc_u32pair(acc[4], acc[5], vh.z); acc_u32pair(acc[4], acc[5], vl.z);
            acc_u32pair(acc[6], acc[7], vh.w); acc_u32pair(acc[6], acc[7], vl.w);
        } else {
            uint2 vh = *reinterpret_cast<const uint2*>(rh + u0);
            uint2 vl = *reinterpret_cast<const uint2*>(rl + u0);
            acc_u32pair(acc[0], acc[1], vh.x); acc_u32pair(acc[0], acc[1], vl.x);
            acc_u32pair(acc[2], acc[3], vh.y); acc_u32pair(acc[2], acc[3], vl.y);
        }
    };

    int j = beg;
    for (; j + 4 <= end; j += 4) {
        int s0 = __ldg(&g_srcs[j + 0]);
        int s1 = __ldg(&g_srcs[j + 1]);
        int s2 = __ldg(&g_srcs[j + 2]);
        int s3 = __ldg(&g_srcs[j + 3]);
        gather_one(s0); gather_one(s1); gather_one(s2); gather_one(s3);
    }
    for (; j < end; ++j) gather_one(__ldg(&g_srcs[j]));

    float inv = 1.0f / fmaxf((float)len, 1.0f);
    uint32_t oh[NU], ol[NU];
#pragma unroll
    for (int u = 0; u < NU; ++u) {
        __nv_bfloat16 ha, la, hb, lb;
        split_bf16(acc[2 * u + 0] * inv, ha, la);
        split_bf16(acc[2 * u + 1] * inv, hb, lb);
        oh[u] = pack2(ha, hb);
        ol[u] = pack2(la, lb);
    }
    uint32_t* wh = reinterpret_cast<uint32_t*>(g_aggh + (size_t)node * C);
    uint32_t* wl = reinterpret_cast<uint32_t*>(g_aggl + (size_t)node * C);
    if (NU == 4) {
        *reinterpret_cast<uint4*>(wh + u0) = make_uint4(oh[0], oh[1], oh[2], oh[3]);
        *reinterpret_cast<uint4*>(wl + u0) = make_uint4(ol[0], ol[1], ol[2], ol[3]);
    } else {
        *reinterpret_cast<uint2*>(wh + u0) = make_uint2(oh[0], oh[1]);
        *reinterpret_cast<uint2*>(wl + u0) = make_uint2(ol[0], ol[1]);
    }
}

// ---------------------------------------------------------------------------
// fused dual-GEMM: C = agg@W_l + A2@W_r + bias (+relu)
//   split hi/lo smem tiles staged by cp.async (2-stage), direct bf16x2
//   fragment LDS (no PRMT), 3 mma products.
// NOTE: SBF*2 (row stride in bytes) MUST be a multiple of 16 for cp.async.
// ---------------------------------------------------------------------------
#define BM 128
#define BN 128
#define SBF 40                                  // bf16 per smem row -> 80 B
#define TILE_BF (128 * SBF)                     // 5120 bf16 per tile
#define STG_BF (4 * TILE_BF)                    // Ah, Al, Bh, Bl
#define SMEM_BYTES (2 * STG_BF * 2)             // 81920

__global__ __launch_bounds__(256, 2)
void k_gemm(int a2sel, int woff_l, int woff_r,
            const float* __restrict__ bias,
            float* __restrict__ Cext, int osel,   // 0=ext fp32, 1=h0, 2=h1
            int K, int relu) {
    extern __shared__ __nv_bfloat16 sm[];
    const uint32_t sb = smem_u32p(sm);

    const __nv_bfloat16* A2h = (a2sel == 0) ? g_xh : (a2sel == 1 ? g_h0h : g_h1h);
    const __nv_bfloat16* A2l = (a2sel == 0) ? g_xl : (a2sel == 1 ? g_h0l : g_h1l);

    const int tid  = threadIdx.x;
    const int wid  = tid >> 5;
    const int lane = tid & 31;
    const int wm   = wid & 3;
    const int wn   = wid >> 2;
    const int bm   = blockIdx.x * BM;
    const int bn   = blockIdx.y * BN;
    const int r4   = lane >> 2;
    const int c2   = (lane & 3) * 2;

    const int KCH = K / 32;
    const int NCH = 2 * KCH;

    float acc[2][8][4];
#pragma unroll
    for (int mt = 0; mt < 2; mt++)
#pragma unroll
        for (int nt = 0; nt < 8; nt++)
#pragma unroll
            for (int q = 0; q < 4; q++) acc[mt][nt][q] = 0.0f;

    auto issue = [&](int c) {
        int part = (c >= KCH) ? 1 : 0;
        int k0 = (c - part * KCH) * 32;
        const __nv_bfloat16* Ah = part ? A2h : g_aggh;
        const __nv_bfloat16* Al = part ? A2l : g_aggl;
        const __nv_bfloat16* Bh = g_Wh + (part ? woff_r : woff_l);
        const __nv_bfloat16* Bl = g_Wl + (part ? woff_r : woff_l);
        uint32_t st = sb + (c & 1) * (STG_BF * 2);
#pragma unroll
        for (int it = 0; it < 2; ++it) {
            int f = tid + 256 * it;
            int row = f >> 2, q = f & 3;
            int rg = bm + row;
            size_t go = (size_t)rg * K + k0 + q * 8;
            uint32_t so = row * (SBF * 2) + q * 16;
            int sz = (rg < NN) ? 16 : 0;
            cpa16(st + so, Ah + go, sz);
            cpa16(st + TILE_BF * 2 + so, Al + go, sz);
        }
#pragma unroll
        for (int it = 0; it < 2; ++it) {
            int f = tid + 256 * it;
            int n = f >> 2, q = f & 3;
            size_t go = (size_t)(bn + n) * K + k0 + q * 8;
            uint32_t so = n * (SBF * 2) + q * 16;
            cpa16(st + 2 * TILE_BF * 2 + so, Bh + go, 16);
            cpa16(st + 3 * TILE_BF * 2 + so, Bl + go, 16);
        }
        asm volatile("cp.async.commit_group;" ::: "memory");
    };

    issue(0);
    if (NCH > 1) issue(1);

#pragma unroll 1
    for (int c = 0; c < NCH; ++c) {
        if (c + 1 < NCH)
            asm volatile("cp.async.wait_group 1;" ::: "memory");
        else
            asm volatile("cp.async.wait_group 0;" ::: "memory");
        __syncthreads();

        const __nv_bfloat16* sAh = sm + (c & 1) * STG_BF;
        const __nv_bfloat16* sAl = sAh + TILE_BF;
        const __nv_bfloat16* sBh = sAl + TILE_BF;
        const __nv_bfloat16* sBl = sBh + TILE_BF;

#pragma unroll
        for (int kk = 0; kk < 32; kk += 16) {
            uint32_t ah[2][4], al[2][4];
#pragma unroll
            for (int mt = 0; mt < 2; ++mt) {
                int rb = (wm * 32 + mt * 16 + r4) * SBF + kk + c2;
                ah[mt][0] = *reinterpret_cast<const uint32_t*>(&sAh[rb]);
                ah[mt][1] = *reinterpret_cast<const uint32_t*>(&sAh[rb + 8 * SBF]);
                ah[mt][2] = *reinterpret_cast<const uint32_t*>(&sAh[rb + 8]);
                ah[mt][3] = *reinterpret_cast<const uint32_t*>(&sAh[rb + 8 * SBF + 8]);
                al[mt][0] = *reinterpret_cast<const uint32_t*>(&sAl[rb]);
                al[mt][1] = *reinterpret_cast<const uint32_t*>(&sAl[rb + 8 * SBF]);
                al[mt][2] = *reinterpret_cast<const uint32_t*>(&sAl[rb + 8]);
                al[mt][3] = *reinterpret_cast<const uint32_t*>(&sAl[rb + 8 * SBF + 8]);
            }
#pragma unroll
            for (int nt = 0; nt < 8; ++nt) {
                int nb = (wn * 64 + nt * 8 + r4) * SBF + kk + c2;
                uint32_t bh[2], bl[2];
                bh[0] = *reinterpret_cast<const uint32_t*>(&sBh[nb]);
                bh[1] = *reinterpret_cast<const uint32_t*>(&sBh[nb + 8]);
                bl[0] = *reinterpret_cast<const uint32_t*>(&sBl[nb]);
                bl[1] = *reinterpret_cast<const uint32_t*>(&sBl[nb + 8]);
#pragma unroll
                for (int mt = 0; mt < 2; ++mt) {
                    mma_bf16(acc[mt][nt], ah[mt], bh);
                    mma_bf16(acc[mt][nt], al[mt], bh);
                    mma_bf16(acc[mt][nt], ah[mt], bl);
                }
            }
        }
        __syncthreads();
        if (c + 2 < NCH) issue(c + 2);
    }

    // ---- epilogue ----
    __nv_bfloat16* Ch = (osel == 1) ? g_h0h : g_h1h;
    __nv_bfloat16* Cl = (osel == 1) ? g_h0l : g_h1l;
#pragma unroll
    for (int nt = 0; nt < 8; ++nt) {
        int col = bn + wn * 64 + nt * 8 + c2;
        float2 bv = *reinterpret_cast<const float2*>(bias + col);
#pragma unroll
        for (int mt = 0; mt < 2; ++mt) {
            int row0 = bm + wm * 32 + mt * 16 + r4;
            float2 o0, o1;
            o0.x = acc[mt][nt][0] + bv.x;
            o0.y = acc[mt][nt][1] + bv.y;
            o1.x = acc[mt][nt][2] + bv.x;
            o1.y = acc[mt][nt][3] + bv.y;
            if (relu) {
                o0.x = fmaxf(o0.x, 0.f); o0.y = fmaxf(o0.y, 0.f);
                o1.x = fmaxf(o1.x, 0.f); o1.y = fmaxf(o1.y, 0.f);
            }
            if (osel == 0) {
                if (row0 < NN)
                    *reinterpret_cast<float2*>(Cext + (size_t)row0 * 256 + col) = o0;
                if (row0 + 8 < NN)
                    *reinterpret_cast<float2*>(Cext + (size_t)(row0 + 8) * 256 + col) = o1;
            } else {
                if (row0 < NN) {
                    __nv_bfloat16 ha, la, hb, lb;
                    split_bf16(o0.x, ha, la);
                    split_bf16(o0.y, hb, lb);
                    *reinterpret_cast<uint32_t*>(Ch + (size_t)row0 * 256 + col) = pack2(ha, hb);
                    *reinterpret_cast<uint32_t*>(Cl + (size_t)row0 * 256 + col) = pack2(la, lb);
                }
                if (row0 + 8 < NN) {
                    __nv_bfloat16 ha, la, hb, lb;
                    split_bf16(o1.x, ha, la);
                    split_bf16(o1.y, hb, lb);
                    *reinterpret_cast<uint32_t*>(Ch + (size_t)(row0 + 8) * 256 + col) = pack2(ha, hb);
                    *reinterpret_cast<uint32_t*>(Cl + (size_t)(row0 + 8) * 256 + col) = pack2(la, lb);
                }
            }
        }
    }
}

// ---------------------------------------------------------------------------
// launch (single stream, serial fused schedule)
// ---------------------------------------------------------------------------
extern "C" void kernel_launch(void* const* d_in, const int* in_sizes, int n_in,
                              void* d_out, int out_size) {
    const float* x    = (const float*)d_in[0];
    const float* W_l0 = (const float*)d_in[1];
    const float* b_l0 = (const float*)d_in[2];
    const float* W_r0 = (const float*)d_in[3];
    const float* W_l1 = (const float*)d_in[4];
    const float* b_l1 = (const float*)d_in[5];
    const float* W_r1 = (const float*)d_in[6];
    const float* W_l2 = (const float*)d_in[7];
    const float* b_l2 = (const float*)d_in[8];
    const float* W_r2 = (const float*)d_in[9];
    const int*   src  = (const int*)d_in[10];
    const int*   dst  = (const int*)d_in[11];
    float*       out  = (float*)d_out;

    const int T = 256;
    dim3 gg((NN + BM - 1) / BM, 256 / BN);

    cudaFuncSetAttribute(k_gemm, cudaFuncAttributeMaxDynamicSharedMemorySize, SMEM_BYTES);

    // ---- CSR build ----
    k_zero_cnt<<<(NN + T - 1) / T, T>>>();
    k_hist<<<(NE + T - 1) / T, T>>>(dst);
    k_scan1<<<NB1, SCAN_B>>>();
    k_scan2<<<1, 256>>>();
    k_scan3<<<(NN + T - 1) / T, T>>>();
    k_place<<<(NE + T - 1) / T, T>>>(src, dst);

    // ---- prep ----
    k_prep_x<<<(NN * 64 + T - 1) / T, T>>>(x);
    k_prep_w<<<(128 * 256 + T - 1) / T, T>>>(W_l0, 128, 0);
    k_prep_w<<<(128 * 256 + T - 1) / T, T>>>(W_r0, 128, 32768);
    k_prep_w<<<(256 * 256 + T - 1) / T, T>>>(W_l1, 256, 65536);
    k_prep_w<<<(256 * 256 + T - 1) / T, T>>>(W_r1, 256, 131072);
    k_prep_w<<<(256 * 256 + T - 1) / T, T>>>(W_l2, 256, 196608);
    k_prep_w<<<(256 * 256 + T - 1) / T, T>>>(W_r2, 256, 262144);

    // ---- layer 0 (K = 128) ----
    k_aggregate<128><<<(NN * 32 + T - 1) / T, T>>>(0);
    k_gemm<<<gg, T, SMEM_BYTES>>>(0, 0, 32768, b_l0, nullptr, 1, 128, 1);

    // ---- layer 1 (K = 256) ----
    k_aggregate<256><<<(NN * 32 + T - 1) / T, T>>>(1);
    k_gemm<<<gg, T, SMEM_BYTES>>>(1, 65536, 131072, b_l1, nullptr, 2, 256, 1);

    // ---- layer 2 (K = 256, no relu, write d_out) ----
    k_aggregate<256><<<(NN * 32 + T - 1) / T, T>>>(2);
    k_gemm<<<gg, T, SMEM_BYTES>>>(2, 196608, 262144, b_l2, out, 0, 256, 0);
}